// round 16
// baseline (speedup 1.0000x reference)
#include <cuda_runtime.h>

#define CIN  128
#define PP   784          // 28*28
#define NPIX 3136         // 4*784
#define PIMG 900          // 30*30 padded image
#define PADN 3600         // 4*900 per channel
#define NBLK 294
typedef unsigned long long ull;

// ---------------- scratch (device globals; no allocation) ----------------
__device__ __align__(16) float g_y1 [CIN * NPIX];     // conv1x1 out, [c][q]
__device__ __align__(16) float g_zp [CIN * PADN];     // z (bn1+relu), zero-padded 30x30
__device__ __align__(16) float g_p3 [6][CIN * NPIX];  // conv3x3 (kh,ciHalf) partials
__device__ __align__(16) float g_y3p[CIN * PADN];     // conv3x3 combined, zero-padded
__device__ __align__(16) float g_p4 [6][CIN * NPIX];  // adder3x3 partials (+S)
// transposed weights: [ci][co]
__device__ __align__(16) float g_w1t [CIN * CIN];
__device__ __align__(16) float g_wa1t[CIN * CIN];
__device__ __align__(16) float g_w2t [9][CIN * CIN];
__device__ __align__(16) float g_wa2t[9][CIN * CIN];
// BN1 folded params
__device__ float g_sc1[CIN], g_sh1[CIN];
// grid barrier state (monotone gen; count returns to 0 after each barrier)
__device__ unsigned g_barCnt = 0;
__device__ unsigned g_barGen = 0;

// ---------------- packed f32x2 helpers -----------------------------------
__device__ __forceinline__ ull fma2(ull a, ull b, ull c) {
    ull d; asm("fma.rn.f32x2 %0, %1, %2, %3;" : "=l"(d) : "l"(a), "l"(b), "l"(c)); return d;
}
__device__ __forceinline__ ull add2(ull a, ull b) {
    ull d; asm("add.rn.f32x2 %0, %1, %2;" : "=l"(d) : "l"(a), "l"(b)); return d;
}
__device__ __forceinline__ ull dup2(float w) {
    ull d; asm("mov.b64 %0, {%1, %1};" : "=l"(d) : "f"(w)); return d;
}
__device__ __forceinline__ float lo32(ull v) { return __uint_as_float((unsigned)(v & 0xFFFFFFFFu)); }
__device__ __forceinline__ float hi32(ull v) { return __uint_as_float((unsigned)(v >> 32)); }
#define NEG1X2 0xBF800000BF800000ULL
#define ABSM   0x7FFFFFFF7FFFFFFFULL

// Software grid barrier: all NBLK CTAs must be co-resident (verified: 128 thr,
// <=256 regs, ~25KB smem -> >=2 CTAs/SM on 148 SMs = 296 >= 294).
__device__ __forceinline__ void gridbar() {
    __syncthreads();
    if (threadIdx.x == 0) {
        __threadfence();
        unsigned gen = atomicAdd(&g_barGen, 0u);          // read BEFORE arriving
        if (atomicAdd(&g_barCnt, 1u) == NBLK - 1u) {
            atomicExch(&g_barCnt, 0u);
            __threadfence();
            atomicAdd(&g_barGen, 1u);                     // release
        } else {
            while (atomicAdd(&g_barGen, 0u) == gen) __nanosleep(64);
        }
        __threadfence();
    }
    __syncthreads();
}

// =========================================================================
// Persistent mega-kernel: all phases, one launch, 294 CTAs x 128 threads.
// =========================================================================
__global__ __launch_bounds__(128) void kmega(
    const float* __restrict__ x,
    const float* __restrict__ w1,  const float* __restrict__ wa1,
    const float* __restrict__ g1,  const float* __restrict__ b1,
    const float* __restrict__ m1,  const float* __restrict__ v1,
    const float* __restrict__ w2,  const float* __restrict__ wa2,
    const float* __restrict__ g2,  const float* __restrict__ b2,
    const float* __restrict__ m2,  const float* __restrict__ v2,
    float* __restrict__ out)
{
    __shared__ __align__(16) char sbuf[24832];
    float (*sW2)[16][128] = reinterpret_cast<float(*)[16][128]>(sbuf);   // 16KB
    float* sAraw = reinterpret_cast<float*>(sbuf + 16384);               // 8KB
    int*   sT    = reinterpret_cast<int*>(sbuf + 24576);                 // 64 ints

    const int tid = threadIdx.x;
    const int bid = blockIdx.x;

    // ---------------- P0: weight transpose + BN1 fold ----------------
    {
        int i = bid * 128 + tid;
        if (i < CIN * CIN) {
            int ci = i >> 7, co = i & 127;
            g_w1t [ci * CIN + co] = w1 [co * CIN + ci];
            g_wa1t[ci * CIN + co] = wa1[co * CIN + ci];
#pragma unroll
            for (int t = 0; t < 9; t++) {
                g_w2t [t][ci * CIN + co] = w2 [(co * CIN + ci) * 9 + t];
                g_wa2t[t][ci * CIN + co] = wa2[(co * CIN + ci) * 9 + t];
            }
            if (i < CIN) {
                float sc = g1[i] / sqrtf(v1[i] + 1e-5f);
                g_sc1[i] = sc;
                g_sh1[i] = b1[i] - m1[i] * sc;
            }
        }
    }
    gridbar();

    // ---------------- P1: conv1x1 (196 tiles, 16px x 128co) ----------------
    if (bid < 196) {
        float (*sA)[16][16] = reinterpret_cast<float(*)[16][16]>(sAraw);
        const int col = tid & 3, row = tid >> 2;
        const int qBase = bid * 16;
        if (tid < 16) {
            int q = qBase + tid;
            int n = q / PP, p = q - n * PP;
            sT[tid] = n * CIN * PP + p;
        }
        __syncthreads();
        ull acc[4][2];
#pragma unroll
        for (int i = 0; i < 4; i++) { acc[i][0] = 0; acc[i][1] = 0; }
        float aReg[2]; float4 wReg[4];
        auto ldg = [&](int s) {
            int ci0 = s << 4;
#pragma unroll
            for (int k = 0; k < 2; k++) {
                int e = k * 128 + tid;
                aReg[k] = x[sT[e & 15] + (ci0 + (e >> 4)) * PP];
            }
#pragma unroll
            for (int k = 0; k < 4; k++) {
                int e4 = (k * 128 + tid) * 4;
                wReg[k] = *(const float4*)&g_w1t[(ci0 + (e4 >> 7)) * CIN + (e4 & 127)];
            }
        };
        auto sts = [&](int b) {
#pragma unroll
            for (int k = 0; k < 2; k++) { int e = k * 128 + tid; sA[b][e >> 4][e & 15] = aReg[k]; }
#pragma unroll
            for (int k = 0; k < 4; k++) { int e4 = (k * 128 + tid) * 4; *(float4*)&sW2[b][e4 >> 7][e4 & 127] = wReg[k]; }
        };
        ldg(0); sts(0); __syncthreads();
        for (int s = 0; s < 8; s++) {
            int b = s & 1;
            if (s < 7) ldg(s + 1);
#pragma unroll
            for (int ci = 0; ci < 16; ci++) {
                ulonglong2 a01 = *(const ulonglong2*)&sA[b][ci][col * 4];
                float4 w4 = *(const float4*)&sW2[b][ci][row * 4];
                float wf[4] = {w4.x, w4.y, w4.z, w4.w};
#pragma unroll
                for (int i = 0; i < 4; i++) {
                    ull wd = dup2(wf[i]);
                    acc[i][0] = fma2(wd, a01.x, acc[i][0]);
                    acc[i][1] = fma2(wd, a01.y, acc[i][1]);
                }
            }
            if (s < 7) sts(b ^ 1);
            __syncthreads();
        }
        const int q = qBase + col * 4;
#pragma unroll
        for (int i = 0; i < 4; i++) {
            int co = row * 4 + i;
            *(ull*)&g_y1[co * NPIX + q]     = acc[i][0];
            *(ull*)&g_y1[co * NPIX + q + 2] = acc[i][1];
        }
    }
    gridbar();

    // ---------------- P2: adder1x1 + BN1 + ReLU -> padded g_zp ----------------
    if (bid < 196) {
        float (*sA)[16][16] = reinterpret_cast<float(*)[16][16]>(sAraw);
        const int col = tid & 3, row = tid >> 2;
        const int qBase = bid * 16;
        if (tid < 16) {
            int q = qBase + tid;
            int n = q / PP, p = q - n * PP;
            int h = p / 28, w = p - h * 28;
            sT[tid] = n * PIMG + (h + 1) * 30 + w + 1;
        }
        __syncthreads();
        ull acc[4][2];
#pragma unroll
        for (int i = 0; i < 4; i++) { acc[i][0] = 0; acc[i][1] = 0; }
        float aReg[2]; float4 wReg[4];
        auto ldg = [&](int s) {
            int ci0 = s << 4;
#pragma unroll
            for (int k = 0; k < 2; k++) {
                int e = k * 128 + tid;
                aReg[k] = g_y1[(ci0 + (e >> 4)) * NPIX + qBase + (e & 15)];
            }
#pragma unroll
            for (int k = 0; k < 4; k++) {
                int e4 = (k * 128 + tid) * 4;
                wReg[k] = *(const float4*)&g_wa1t[(ci0 + (e4 >> 7)) * CIN + (e4 & 127)];
            }
        };
        auto sts = [&](int b) {
#pragma unroll
            for (int k = 0; k < 2; k++) { int e = k * 128 + tid; sA[b][e >> 4][e & 15] = aReg[k]; }
#pragma unroll
            for (int k = 0; k < 4; k++) { int e4 = (k * 128 + tid) * 4; *(float4*)&sW2[b][e4 >> 7][e4 & 127] = wReg[k]; }
        };
        ldg(0); sts(0); __syncthreads();
        for (int s = 0; s < 8; s++) {
            int b = s & 1;
            if (s < 7) ldg(s + 1);
#pragma unroll
            for (int ci = 0; ci < 16; ci++) {
                ulonglong2 a01 = *(const ulonglong2*)&sA[b][ci][col * 4];
                float4 w4 = *(const float4*)&sW2[b][ci][row * 4];
                float wf[4] = {w4.x, w4.y, w4.z, w4.w};
#pragma unroll
                for (int i = 0; i < 4; i++) {
                    ull wd = dup2(wf[i]);
                    acc[i][0] = add2(acc[i][0], fma2(wd, NEG1X2, a01.x) & ABSM);
                    acc[i][1] = add2(acc[i][1], fma2(wd, NEG1X2, a01.y) & ABSM);
                }
            }
            if (s < 7) sts(b ^ 1);
            __syncthreads();
        }
#pragma unroll
        for (int i = 0; i < 4; i++) {
            int co = row * 4 + i;
            float sc = g_sc1[co], sh = g_sh1[co];
            float r0 = fmaxf(fmaf(-lo32(acc[i][0]), sc, sh), 0.f);
            float r1 = fmaxf(fmaf(-hi32(acc[i][0]), sc, sh), 0.f);
            float r2 = fmaxf(fmaf(-lo32(acc[i][1]), sc, sh), 0.f);
            float r3 = fmaxf(fmaf(-hi32(acc[i][1]), sc, sh), 0.f);
            float* zc = &g_zp[co * PADN];
            zc[sT[col * 4]]     = r0;
            zc[sT[col * 4 + 1]] = r1;
            zc[sT[col * 4 + 2]] = r2;
            zc[sT[col * 4 + 3]] = r3;
        }
    }
    gridbar();

    // ---------------- P3: conv3x3 (294 tiles; R13 winner geometry) ----------
    {
        float (*sA)[16][64] = reinterpret_cast<float(*)[16][64]>(sAraw);
        const int col = tid & 7, row = tid >> 3;
        const int qi = bid % 49, yi = bid / 49;
        const int qBase  = qi * 64;
        const int kh     = yi >> 1;
        const int ciBase = (yi & 1) * 64;
        if (tid < 64) {
            int q = qBase + tid;
            int n = q / PP, p = q - n * PP;
            int h = p / 28, w = p - h * 28;
            sT[tid] = n * PIMG + (h + kh) * 30 + w;
        }
        __syncthreads();
        ull acc[8][4];
#pragma unroll
        for (int i = 0; i < 8; i++)
#pragma unroll
            for (int j = 0; j < 4; j++) acc[i][j] = 0;
        float aReg[8]; float4 wReg[4];
        auto ldg = [&](int s) {
            int kw = s >> 2, ciOff = (s & 3) << 4;
            int cB = ciBase + ciOff;
#pragma unroll
            for (int k = 0; k < 8; k++) {
                int e = k * 128 + tid;
                aReg[k] = g_zp[(cB + (e >> 6)) * PADN + sT[e & 63] + kw];
            }
            const float* __restrict__ wslice = &g_w2t[kh * 3 + kw][0];
#pragma unroll
            for (int k = 0; k < 4; k++) {
                int e4 = (k * 128 + tid) * 4;
                wReg[k] = *(const float4*)&wslice[(cB + (e4 >> 7)) * CIN + (e4 & 127)];
            }
        };
        auto sts = [&](int b) {
#pragma unroll
            for (int k = 0; k < 8; k++) { int e = k * 128 + tid; sA[b][e >> 6][e & 63] = aReg[k]; }
#pragma unroll
            for (int k = 0; k < 4; k++) { int e4 = (k * 128 + tid) * 4; *(float4*)&sW2[b][e4 >> 7][e4 & 127] = wReg[k]; }
        };
        ldg(0); sts(0); __syncthreads();
        for (int s = 0; s < 12; s++) {
            int b = s & 1;
            if (s < 11) ldg(s + 1);
#pragma unroll
            for (int ci = 0; ci < 16; ci++) {
                ulonglong2 a01 = *(const ulonglong2*)&sA[b][ci][col * 8];
                ulonglong2 a23 = *(const ulonglong2*)&sA[b][ci][col * 8 + 4];
                float4 wa = *(const float4*)&sW2[b][ci][row * 8];
                float4 wb = *(const float4*)&sW2[b][ci][row * 8 + 4];
                float wf[8] = {wa.x, wa.y, wa.z, wa.w, wb.x, wb.y, wb.z, wb.w};
#pragma unroll
                for (int i = 0; i < 8; i++) {
                    ull wd = dup2(wf[i]);
                    acc[i][0] = fma2(wd, a01.x, acc[i][0]);
                    acc[i][1] = fma2(wd, a01.y, acc[i][1]);
                    acc[i][2] = fma2(wd, a23.x, acc[i][2]);
                    acc[i][3] = fma2(wd, a23.y, acc[i][3]);
                }
            }
            if (s < 11) sts(b ^ 1);
            __syncthreads();
        }
        const int q = qBase + col * 8;
        float* __restrict__ o = g_p3[yi];
#pragma unroll
        for (int i = 0; i < 8; i++) {
            int co = row * 8 + i;
#pragma unroll
            for (int j = 0; j < 4; j++)
                *(ull*)&o[co * NPIX + q + 2 * j] = acc[i][j];
        }
    }
    gridbar();

    // ---------------- P4: ky — sum 6 conv partials into padded g_y3p --------
    {
#pragma unroll
        for (int r = 0; r < 3; r++) {
            int e = r * (NBLK * 128) + bid * 128 + tid;
            if (e < 100352) {
                int chunk = e % 7;
                int rowid = e / 7;
                int h = rowid % 28;
                int n = (rowid / 28) & 3;
                int c = rowid / 112;
                int qo = c * NPIX + n * PP + h * 28 + chunk * 4;
                float4 s = *(const float4*)&g_p3[0][qo];
#pragma unroll
                for (int t = 1; t < 6; t++) {
                    float4 a = *(const float4*)&g_p3[t][qo];
                    s.x += a.x; s.y += a.y; s.z += a.z; s.w += a.w;
                }
                int po = c * PADN + n * PIMG + (h + 1) * 30 + 1 + chunk * 4;
                g_y3p[po]     = s.x;
                g_y3p[po + 1] = s.y;
                g_y3p[po + 2] = s.z;
                g_y3p[po + 3] = s.w;
            }
        }
    }
    gridbar();

    // ---------------- P5: adder3x3 (588 tiles, 2 per CTA; R13 geometry) -----
    {
        float (*sA)[16][32] = reinterpret_cast<float(*)[16][32]>(sAraw);
        const int col = tid & 7, row = tid >> 3;
#pragma unroll
        for (int r = 0; r < 2; r++) {
            int t = bid + r * NBLK;
            int qi = t % 98, yi = t / 98;
            const int qBase  = qi * 32;
            const int kh     = yi >> 1;
            const int ciBase = (yi & 1) * 64;
            if (tid < 32) {
                int q = qBase + tid;
                int n = q / PP, p = q - n * PP;
                int h = p / 28, w = p - h * 28;
                sT[tid] = n * PIMG + (h + kh) * 30 + w;
            }
            __syncthreads();
            ull acc[8][2];
#pragma unroll
            for (int i = 0; i < 8; i++) { acc[i][0] = 0; acc[i][1] = 0; }
            float aReg[4]; float4 wReg[4];
            auto ldg = [&](int s) {
                int kw = s >> 2, ciOff = (s & 3) << 4;
                int cB = ciBase + ciOff;
#pragma unroll
                for (int k = 0; k < 4; k++) {
                    int e = k * 128 + tid;
                    aReg[k] = g_y3p[(cB + (e >> 5)) * PADN + sT[e & 31] + kw];
                }
                const float* __restrict__ wslice = &g_wa2t[kh * 3 + kw][0];
#pragma unroll
                for (int k = 0; k < 4; k++) {
                    int e4 = (k * 128 + tid) * 4;
                    wReg[k] = *(const float4*)&wslice[(cB + (e4 >> 7)) * CIN + (e4 & 127)];
                }
            };
            auto sts = [&](int b) {
#pragma unroll
                for (int k = 0; k < 4; k++) { int e = k * 128 + tid; sA[b][e >> 5][e & 31] = aReg[k]; }
#pragma unroll
                for (int k = 0; k < 4; k++) { int e4 = (k * 128 + tid) * 4; *(float4*)&sW2[b][e4 >> 7][e4 & 127] = wReg[k]; }
            };
            ldg(0); sts(0); __syncthreads();
            for (int s = 0; s < 12; s++) {
                int b = s & 1;
                if (s < 11) ldg(s + 1);
#pragma unroll
                for (int ci = 0; ci < 16; ci++) {
                    ulonglong2 av = *(const ulonglong2*)&sA[b][ci][col * 4];
                    float4 wa = *(const float4*)&sW2[b][ci][row * 8];
                    float4 wb = *(const float4*)&sW2[b][ci][row * 8 + 4];
                    float wf[8] = {wa.x, wa.y, wa.z, wa.w, wb.x, wb.y, wb.z, wb.w};
#pragma unroll
                    for (int i = 0; i < 8; i++) {
                        ull wd = dup2(wf[i]);
                        acc[i][0] = add2(acc[i][0], fma2(wd, NEG1X2, av.x) & ABSM);
                        acc[i][1] = add2(acc[i][1], fma2(wd, NEG1X2, av.y) & ABSM);
                    }
                }
                if (s < 11) sts(b ^ 1);
                __syncthreads();
            }
            const int q = qBase + col * 4;
            float* __restrict__ o = g_p4[yi];
#pragma unroll
            for (int i = 0; i < 8; i++) {
                int co = row * 8 + i;
                *(ull*)&o[co * NPIX + q]     = acc[i][0];
                *(ull*)&o[co * NPIX + q + 2] = acc[i][1];
            }
            __syncthreads();
        }
    }
    gridbar();

    // ---------------- P6: epilogue ------------------------------------------
    {
#pragma unroll
        for (int r = 0; r < 3; r++) {
            int e = r * (NBLK * 128) + bid * 128 + tid;
            if (e < 100352) {
                int base = e * 4;
                int c = base / NPIX;
                int q = base - c * NPIX;
                int n = q / PP, p = q - n * PP;
                float scale = g2[c] / sqrtf(v2[c] + 1e-5f);
                float shift = b2[c] - m2[c] * scale;
                float4 s = *(const float4*)&g_p4[0][base];
#pragma unroll
                for (int t = 1; t < 6; t++) {
                    float4 a = *(const float4*)&g_p4[t][base];
                    s.x += a.x; s.y += a.y; s.z += a.z; s.w += a.w;
                }
                int xi = (n * CIN + c) * PP + p;
                float4 xr = *(const float4*)&x[xi];
                float4 rr;
                rr.x = fmaxf(fmaxf(fmaf(-s.x, scale, shift), 0.f) + xr.x, 0.f);
                rr.y = fmaxf(fmaxf(fmaf(-s.y, scale, shift), 0.f) + xr.y, 0.f);
                rr.z = fmaxf(fmaxf(fmaf(-s.z, scale, shift), 0.f) + xr.z, 0.f);
                rr.w = fmaxf(fmaxf(fmaf(-s.w, scale, shift), 0.f) + xr.w, 0.f);
                *(float4*)&out[xi] = rr;
            }
        }
    }
}

// =========================================================================
extern "C" void kernel_launch(void* const* d_in, const int* in_sizes, int n_in,
                              void* d_out, int out_size) {
    const float* x   = (const float*)d_in[0];
    const float* w1  = (const float*)d_in[1];
    const float* wa1 = (const float*)d_in[2];
    const float* g1  = (const float*)d_in[3];
    const float* b1  = (const float*)d_in[4];
    const float* m1  = (const float*)d_in[5];
    const float* v1  = (const float*)d_in[6];
    const float* w2  = (const float*)d_in[7];
    const float* wa2 = (const float*)d_in[8];
    const float* g2  = (const float*)d_in[9];
    const float* b2  = (const float*)d_in[10];
    const float* m2  = (const float*)d_in[11];
    const float* v2  = (const float*)d_in[12];
    float* out = (float*)d_out;

    kmega<<<NBLK, 128>>>(x, w1, wa1, g1, b1, m1, v1, w2, wa2, g2, b2, m2, v2, out);
}